// round 2
// baseline (speedup 1.0000x reference)
#include <cuda_runtime.h>
#include <cstddef>

#define HWSZ 40000
#define CD   128

// ---- scratch (static device globals; no runtime allocation) ----
__device__ float g_kv[4UL * 256 * 40000];     // conv output [n][o][pos]
__device__ float g_tmp[2UL * 40000 * 128];    // q after head 0 (channels-last)
__device__ float g_tmp2[2UL * 40000 * 128];   // q after head 1 (channels-last)

// ---------------------------------------------------------------------------
// 1x1 conv as GEMM: g_kv[n][o][pos] = sum_c W[o][c] * X[n][pos][c]
// grid (157 pos-tiles, 4 o-blocks of 64, 4 n), block 256.
// Tile: 64 o x 256 pos, K-chunks of 32. Thread: 8 o x 8 pos.
// ---------------------------------------------------------------------------
__global__ void __launch_bounds__(256) conv_kernel(const float* __restrict__ x,
                                                   const float* __restrict__ w) {
    __shared__ float Ws[32 * 72];    // [c][o_local], pad 72 (16B-aligned rows)
    __shared__ float Xs[32 * 260];   // [c][p_local], pad 260
    const int tid = threadIdx.x;
    const int p0 = blockIdx.x * 256;
    const int o0 = blockIdx.y * 64;
    const int n  = blockIdx.z;
    const float* Xg = x + (size_t)n * HWSZ * CD;
    const float* Wg = w + (size_t)o0 * CD;
    const int tx = tid & 31;   // pos group: p = p0 + tx*8 + j
    const int ty = tid >> 5;   // o group:   o = o0 + ty*8 + i

    float acc[8][8];
#pragma unroll
    for (int i = 0; i < 8; i++)
#pragma unroll
        for (int j = 0; j < 8; j++) acc[i][j] = 0.f;

    for (int cc = 0; cc < CD; cc += 32) {
#pragma unroll
        for (int it = 0; it < 8; it++) {              // 64o x 32c = 2048 elems
            int idx = tid + it * 256;
            int ol = idx >> 5, c = idx & 31;
            Ws[c * 72 + ol] = Wg[(size_t)ol * CD + cc + c];
        }
#pragma unroll
        for (int it = 0; it < 32; it++) {             // 256p x 32c = 8192 elems
            int idx = tid + it * 256;
            int pl = idx >> 5, c = idx & 31;
            int gp = p0 + pl;
            Xs[c * 260 + pl] = (gp < HWSZ) ? Xg[(size_t)gp * CD + cc + c] : 0.f;
        }
        __syncthreads();
#pragma unroll 4
        for (int c = 0; c < 32; c++) {
            float4 w0 = *(const float4*)&Ws[c * 72 + ty * 8];
            float4 w1 = *(const float4*)&Ws[c * 72 + ty * 8 + 4];
            float4 x0 = *(const float4*)&Xs[c * 260 + tx * 8];
            float4 x1 = *(const float4*)&Xs[c * 260 + tx * 8 + 4];
            float wr[8] = {w0.x, w0.y, w0.z, w0.w, w1.x, w1.y, w1.z, w1.w};
            float xr[8] = {x0.x, x0.y, x0.z, x0.w, x1.x, x1.y, x1.z, x1.w};
#pragma unroll
            for (int i = 0; i < 8; i++)
#pragma unroll
                for (int j = 0; j < 8; j++)
                    acc[i][j] = fmaf(wr[i], xr[j], acc[i][j]);
        }
        __syncthreads();
    }

    const int pbase = p0 + tx * 8;
    if (pbase < HWSZ) {   // 40000 % 8 == 0 -> all-or-nothing per thread
        float* O = g_kv + (size_t)n * 256 * HWSZ;
#pragma unroll
        for (int i = 0; i < 8; i++) {
            int o = o0 + ty * 8 + i;
            float4 v0 = make_float4(acc[i][0], acc[i][1], acc[i][2], acc[i][3]);
            float4 v1 = make_float4(acc[i][4], acc[i][5], acc[i][6], acc[i][7]);
            *(float4*)&O[(size_t)o * HWSZ + pbase]     = v0;
            *(float4*)&O[(size_t)o * HWSZ + pbase + 4] = v1;
        }
    }
}

// ---------------------------------------------------------------------------
// Dilate attention, one temporal head.
// Thread = one (b, nh, pos). Gather:
//   G = ((nh*32+hd)*9+kk)*40000 + pos ; M = G/25600 ; L = G%25600
//   val = mask ? blk[(M/9)*25600 + L + di*128 + dj] : 0
// grid (625 pos-tiles of 64, 2 b), block 256 (= 64 pos x 4 nh).
// ---------------------------------------------------------------------------
__global__ void __launch_bounds__(256, 2) attn_kernel(const float* __restrict__ qext,
                                                      int head, int dil, int stage) {
    __shared__ int2  tab[1800];         // {off = (m/9)*25600 + di*128 + dj, packed(di,dj)}
    __shared__ float st[64 * 129];      // output staging, padded rows
    const int tid = threadIdx.x;

    for (int m = tid; m < 1800; m += 256) {
        int c200 = m / 9;
        int kk = m - c200 * 9;
        int i = kk / 3;
        int j = kk - i * 3;
        int di = (i - 1) * dil;
        int dj = (j - 1) * dil;
        tab[m] = make_int2(c200 * 25600 + di * 128 + dj,
                           (di << 16) | (dj & 0xFFFF));
    }
    __syncthreads();

    const float* qin = stage ? g_tmp : qext;
    float* qout      = stage ? g_tmp2 : g_tmp;

    const int b   = blockIdx.y;
    const int pl  = tid & 63;          // pos within tile
    const int nh  = tid >> 6;          // head-group 0..3
    const int pos0 = blockIdx.x * 64;
    const int pos  = pos0 + pl;        // always < 40000 (625*64 == 40000)

    const float* Qf = qin + (size_t)b * HWSZ * CD;
    const float* Kb = g_kv + ((size_t)(2 * b) * 256 + head * 128) * HWSZ;
    const float* Vb = g_kv + ((size_t)(2 * b + 1) * 256 + head * 128) * HWSZ;

    // initial (M, L) for r9 = nh*288
    const int G0 = nh * 288 * 40000 + pos;
    const int m0 = G0 / 25600;
    const int l0 = G0 - m0 * 25600;

    // ---- pass 1: scores ----
    float sc[9];
#pragma unroll
    for (int k = 0; k < 9; k++) sc[k] = 0.f;

    int M = m0, L = l0;
#pragma unroll 1
    for (int hd = 0; hd < 32; hd++) {
        float qv = Qf[(size_t)(nh * 32 + hd) * HWSZ + pos];
#pragma unroll
        for (int kk = 0; kk < 9; kk++) {
            int2 t = tab[M];
            int lw = L >> 7, lc = L & 127;
            int di = t.y >> 16;
            int dj = (int)(short)(t.y & 0xFFFF);
            bool ok = ((unsigned)(lw + di) < 200u) && ((unsigned)(lc + dj) < 128u);
            float kv = ok ? __ldg(&Kb[t.x + L]) : 0.f;
            sc[kk] = fmaf(qv, kv, sc[kk]);
            M += 1; L += 14400;
            if (L >= 25600) { L -= 25600; M += 1; }
        }
    }

    // ---- softmax over 9 ----
    const float SCALE = 0.17677669529663687f;   // 32^-0.5
    float mx = -1e30f;
#pragma unroll
    for (int k = 0; k < 9; k++) { sc[k] *= SCALE; mx = fmaxf(mx, sc[k]); }
    float sum = 0.f;
#pragma unroll
    for (int k = 0; k < 9; k++) { sc[k] = __expf(sc[k] - mx); sum += sc[k]; }
    float inv = 1.0f / sum;
#pragma unroll
    for (int k = 0; k < 9; k++) sc[k] *= inv;

    // ---- pass 2: output, streamed straight into staging smem ----
    M = m0; L = l0;
#pragma unroll 1
    for (int hd = 0; hd < 32; hd++) {
        float o = 0.f;
#pragma unroll
        for (int kk = 0; kk < 9; kk++) {
            int2 t = tab[M];
            int lw = L >> 7, lc = L & 127;
            int di = t.y >> 16;
            int dj = (int)(short)(t.y & 0xFFFF);
            bool ok = ((unsigned)(lw + di) < 200u) && ((unsigned)(lc + dj) < 128u);
            float vv = ok ? __ldg(&Vb[t.x + L]) : 0.f;
            o = fmaf(sc[kk], vv, o);
            M += 1; L += 14400;
            if (L >= 25600) { L -= 25600; M += 1; }
        }
        st[pl * 129 + nh * 32 + hd] = o;
    }
    __syncthreads();

    // coalesced channels-last writeback: 64 pos x 128 ch contiguous
    float* Ob = qout + (size_t)b * HWSZ * CD + (size_t)pos0 * CD;
#pragma unroll
    for (int it = 0; it < 32; it++) {
        int f = tid + it * 256;          // 0..8191
        int p = f >> 7, c = f & 127;
        Ob[f] = st[p * 129 + c];
    }
}

// ---------------------------------------------------------------------------
// Projection: out[p][co] = sum_c q2[p][c] * Wp[co][c] + bias[co], p in [0,80000)
// grid (313 pos-tiles of 256, 2 co-blocks of 64), block 256.
// ---------------------------------------------------------------------------
__global__ void __launch_bounds__(256) proj_kernel(const float* __restrict__ w,
                                                   const float* __restrict__ bias,
                                                   float* __restrict__ out) {
    __shared__ float Ws[32 * 72];
    __shared__ float Xs[32 * 260];
    const int NP = 2 * HWSZ;
    const int tid = threadIdx.x;
    const int p0 = blockIdx.x * 256;
    const int o0 = blockIdx.y * 64;
    const float* Q = g_tmp2;
    const int tx = tid & 31;
    const int ty = tid >> 5;

    float acc[8][8];
#pragma unroll
    for (int i = 0; i < 8; i++)
#pragma unroll
        for (int j = 0; j < 8; j++) acc[i][j] = 0.f;

    for (int cc = 0; cc < CD; cc += 32) {
#pragma unroll
        for (int it = 0; it < 8; it++) {
            int idx = tid + it * 256;
            int ol = idx >> 5, c = idx & 31;
            Ws[c * 72 + ol] = w[(size_t)(o0 + ol) * CD + cc + c];
        }
#pragma unroll
        for (int it = 0; it < 32; it++) {
            int idx = tid + it * 256;
            int pl = idx >> 5, c = idx & 31;
            int gp = p0 + pl;
            Xs[c * 260 + pl] = (gp < NP) ? Q[(size_t)gp * CD + cc + c] : 0.f;
        }
        __syncthreads();
#pragma unroll 4
        for (int c = 0; c < 32; c++) {
            float4 w0 = *(const float4*)&Ws[c * 72 + ty * 8];
            float4 w1 = *(const float4*)&Ws[c * 72 + ty * 8 + 4];
            float4 x0 = *(const float4*)&Xs[c * 260 + tx * 8];
            float4 x1 = *(const float4*)&Xs[c * 260 + tx * 8 + 4];
            float wr[8] = {w0.x, w0.y, w0.z, w0.w, w1.x, w1.y, w1.z, w1.w};
            float xr[8] = {x0.x, x0.y, x0.z, x0.w, x1.x, x1.y, x1.z, x1.w};
#pragma unroll
            for (int i = 0; i < 8; i++)
#pragma unroll
                for (int j = 0; j < 8; j++)
                    acc[i][j] = fmaf(wr[i], xr[j], acc[i][j]);
        }
        __syncthreads();
    }

    float bs[8];
#pragma unroll
    for (int i = 0; i < 8; i++) bs[i] = bias[o0 + ty * 8 + i];

    const int pbase = p0 + tx * 8;
    if (pbase < NP) {   // 80000 % 8 == 0 -> all-or-nothing per thread
#pragma unroll
        for (int j = 0; j < 8; j++) {
            float4 v0 = make_float4(acc[0][j] + bs[0], acc[1][j] + bs[1],
                                    acc[2][j] + bs[2], acc[3][j] + bs[3]);
            float4 v1 = make_float4(acc[4][j] + bs[4], acc[5][j] + bs[5],
                                    acc[6][j] + bs[6], acc[7][j] + bs[7]);
            float* row = out + (size_t)(pbase + j) * CD + o0 + ty * 8;
            *(float4*)(row)     = v0;
            *(float4*)(row + 4) = v1;
        }
    }
}

extern "C" void kernel_launch(void* const* d_in, const int* in_sizes, int n_in,
                              void* d_out, int out_size) {
    const float* q   = (const float*)d_in[0];
    const float* x   = (const float*)d_in[1];
    const float* kvw = (const float*)d_in[2];
    const float* pw  = (const float*)d_in[3];
    const float* pb  = (const float*)d_in[4];
    float* out = (float*)d_out;

    conv_kernel<<<dim3(157, 4, 4), 256>>>(x, kvw);
    attn_kernel<<<dim3(625, 2), 256>>>(q, /*head=*/0, /*dil=*/1, /*stage=*/0);
    attn_kernel<<<dim3(625, 2), 256>>>(q, /*head=*/1, /*dil=*/2, /*stage=*/1);
    proj_kernel<<<dim3(313, 2), 256>>>(pw, pb, out);
}

// round 3
// speedup vs baseline: 1.0986x; 1.0986x over previous
#include <cuda_runtime.h>
#include <cstddef>

#define HWSZ 40000
#define CD   128

// ---- scratch (static device globals; no runtime allocation) ----
__device__ float g_kv[4UL * 256 * 40000];     // conv output [n][o][pos]
__device__ float g_tmp[2UL * 40000 * 128];    // q after head 0 (channels-last)
__device__ float g_tmp2[2UL * 40000 * 128];   // q after head 1 (channels-last)

// packed f32x2 helpers (FFMA2 is PTX-only; ptxas never auto-fuses)
__device__ __forceinline__ unsigned long long pack2(float v) {
    unsigned long long r;
    asm("mov.b64 %0, {%1, %1};" : "=l"(r) : "r"(__float_as_uint(v)));
    return r;
}
__device__ __forceinline__ void fma2(unsigned long long& acc,
                                     unsigned long long a, unsigned long long b) {
    asm("fma.rn.f32x2 %0, %1, %2, %0;" : "+l"(acc) : "l"(a), "l"(b));
}
__device__ __forceinline__ float lo32(unsigned long long v) {
    return __uint_as_float((unsigned)(v & 0xFFFFFFFFull));
}
__device__ __forceinline__ float hi32(unsigned long long v) {
    return __uint_as_float((unsigned)(v >> 32));
}

// ---------------------------------------------------------------------------
// 1x1 conv as GEMM: g_kv[n][o][pos] = sum_c W[o][c] * X[n][pos][c]
// grid (157 pos-tiles, 4 o-blocks of 64, 4 n), block 256.
// Tile: 64 o x 256 pos, K-chunks of 32. Thread: 8 o x 8 pos (4 f32x2 pairs).
// ---------------------------------------------------------------------------
__global__ void __launch_bounds__(256) conv_kernel(const float* __restrict__ x,
                                                   const float* __restrict__ w) {
    __shared__ float Ws[32 * 72];    // [c][o_local], pad 72 (16B-aligned rows)
    __shared__ float Xs[32 * 260];   // [c][p_local], pad 260 (16B-aligned rows)
    const int tid = threadIdx.x;
    const int p0 = blockIdx.x * 256;
    const int o0 = blockIdx.y * 64;
    const int n  = blockIdx.z;
    const float* Xg = x + (size_t)n * HWSZ * CD;
    const float* Wg = w + (size_t)o0 * CD;
    const int tx = tid & 31;   // pos group: p = p0 + tx*8 + j
    const int ty = tid >> 5;   // o group:   o = o0 + ty*8 + i

    unsigned long long acc[8][4];
#pragma unroll
    for (int i = 0; i < 8; i++)
#pragma unroll
        for (int j = 0; j < 4; j++) acc[i][j] = 0ull;

    for (int cc = 0; cc < CD; cc += 32) {
#pragma unroll
        for (int it = 0; it < 8; it++) {              // 64o x 32c = 2048 elems
            int idx = tid + it * 256;
            int ol = idx >> 5, c = idx & 31;
            Ws[c * 72 + ol] = Wg[(size_t)ol * CD + cc + c];
        }
#pragma unroll
        for (int it = 0; it < 32; it++) {             // 256p x 32c = 8192 elems
            int idx = tid + it * 256;
            int pl = idx >> 5, c = idx & 31;
            int gp = p0 + pl;
            Xs[c * 260 + pl] = (gp < HWSZ) ? Xg[(size_t)gp * CD + cc + c] : 0.f;
        }
        __syncthreads();
#pragma unroll 4
        for (int c = 0; c < 32; c++) {
            float4 w0 = *(const float4*)&Ws[c * 72 + ty * 8];
            float4 w1 = *(const float4*)&Ws[c * 72 + ty * 8 + 4];
            const unsigned long long* xp =
                (const unsigned long long*)&Xs[c * 260 + tx * 8];
            unsigned long long xr[4] = {xp[0], xp[1], xp[2], xp[3]};
            unsigned long long wp[8] = {pack2(w0.x), pack2(w0.y), pack2(w0.z), pack2(w0.w),
                                        pack2(w1.x), pack2(w1.y), pack2(w1.z), pack2(w1.w)};
#pragma unroll
            for (int i = 0; i < 8; i++)
#pragma unroll
                for (int j = 0; j < 4; j++)
                    fma2(acc[i][j], wp[i], xr[j]);
        }
        __syncthreads();
    }

    const int pbase = p0 + tx * 8;
    if (pbase < HWSZ) {   // 40000 % 8 == 0 -> all-or-nothing per thread
        float* O = g_kv + (size_t)n * 256 * HWSZ;
#pragma unroll
        for (int i = 0; i < 8; i++) {
            int o = o0 + ty * 8 + i;
            ulonglong2 v0 = make_ulonglong2(acc[i][0], acc[i][1]);
            ulonglong2 v1 = make_ulonglong2(acc[i][2], acc[i][3]);
            *(ulonglong2*)&O[(size_t)o * HWSZ + pbase]     = v0;
            *(ulonglong2*)&O[(size_t)o * HWSZ + pbase + 4] = v1;
        }
    }
}

// ---------------------------------------------------------------------------
// Dilate attention, one temporal head.
// Thread = one (b, nh, pos). Gather:
//   G = ((nh*32+hd)*9+kk)*40000 + pos ; M = G/25600 ; L = G%25600
//   val = mask ? blk[(M/9)*25600 + L + di*128 + dj] : 0
// grid (625 pos-tiles of 64, 2 b), block 256 (= 64 pos x 4 nh).
// ---------------------------------------------------------------------------
__global__ void __launch_bounds__(256, 2) attn_kernel(const float* __restrict__ qext,
                                                      int head, int dil, int stage) {
    __shared__ int2  tab[1800];         // {off = (m/9)*25600 + di*128 + dj, packed(di,dj)}
    __shared__ float st[64 * 129];      // output staging, padded rows
    const int tid = threadIdx.x;

    for (int m = tid; m < 1800; m += 256) {
        int c200 = m / 9;
        int kk = m - c200 * 9;
        int i = kk / 3;
        int j = kk - i * 3;
        int di = (i - 1) * dil;
        int dj = (j - 1) * dil;
        tab[m] = make_int2(c200 * 25600 + di * 128 + dj,
                           (di << 16) | (dj & 0xFFFF));
    }
    __syncthreads();

    const float* qin = stage ? g_tmp : qext;
    float* qout      = stage ? g_tmp2 : g_tmp;

    const int b   = blockIdx.y;
    const int pl  = tid & 63;          // pos within tile
    const int nh  = tid >> 6;          // head-group 0..3
    const int pos0 = blockIdx.x * 64;
    const int pos  = pos0 + pl;        // always < 40000 (625*64 == 40000)

    const float* Qf = qin + (size_t)b * HWSZ * CD;
    const float* Kb = g_kv + ((size_t)(2 * b) * 256 + head * 128) * HWSZ;
    const float* Vb = g_kv + ((size_t)(2 * b + 1) * 256 + head * 128) * HWSZ;

    // initial (M, L) for r9 = nh*288
    const int G0 = nh * 288 * 40000 + pos;
    const int m0 = G0 / 25600;
    const int l0 = G0 - m0 * 25600;

    // ---- pass 1: scores ----
    float sc[9];
#pragma unroll
    for (int k = 0; k < 9; k++) sc[k] = 0.f;

    int M = m0, L = l0;
#pragma unroll 1
    for (int hd = 0; hd < 32; hd++) {
        float qv = Qf[(size_t)(nh * 32 + hd) * HWSZ + pos];
#pragma unroll
        for (int kk = 0; kk < 9; kk++) {
            int2 t = tab[M];
            int lw = L >> 7, lc = L & 127;
            int di = t.y >> 16;
            int dj = (int)(short)(t.y & 0xFFFF);
            bool ok = ((unsigned)(lw + di) < 200u) && ((unsigned)(lc + dj) < 128u);
            float kv = ok ? __ldg(&Kb[t.x + L]) : 0.f;
            sc[kk] = fmaf(qv, kv, sc[kk]);
            M += 1; L += 14400;
            if (L >= 25600) { L -= 25600; M += 1; }
        }
    }

    // ---- softmax over 9 ----
    const float SCALE = 0.17677669529663687f;   // 32^-0.5
    float mx = -1e30f;
#pragma unroll
    for (int k = 0; k < 9; k++) { sc[k] *= SCALE; mx = fmaxf(mx, sc[k]); }
    float sum = 0.f;
#pragma unroll
    for (int k = 0; k < 9; k++) { sc[k] = __expf(sc[k] - mx); sum += sc[k]; }
    float inv = 1.0f / sum;
#pragma unroll
    for (int k = 0; k < 9; k++) sc[k] *= inv;

    // ---- pass 2: output, streamed straight into staging smem ----
    M = m0; L = l0;
#pragma unroll 1
    for (int hd = 0; hd < 32; hd++) {
        float o = 0.f;
#pragma unroll
        for (int kk = 0; kk < 9; kk++) {
            int2 t = tab[M];
            int lw = L >> 7, lc = L & 127;
            int di = t.y >> 16;
            int dj = (int)(short)(t.y & 0xFFFF);
            bool ok = ((unsigned)(lw + di) < 200u) && ((unsigned)(lc + dj) < 128u);
            float vv = ok ? __ldg(&Vb[t.x + L]) : 0.f;
            o = fmaf(sc[kk], vv, o);
            M += 1; L += 14400;
            if (L >= 25600) { L -= 25600; M += 1; }
        }
        st[pl * 129 + nh * 32 + hd] = o;
    }
    __syncthreads();

    // coalesced channels-last writeback: 64 pos x 128 ch contiguous
    float* Ob = qout + (size_t)b * HWSZ * CD + (size_t)pos0 * CD;
#pragma unroll
    for (int it = 0; it < 32; it++) {
        int f = tid + it * 256;          // 0..8191
        int p = f >> 7, c = f & 127;
        Ob[f] = st[p * 129 + c];
    }
}

// ---------------------------------------------------------------------------
// Projection: out[p][co] = sum_c q2[p][c] * Wp[co][c] + bias[co], p in [0,80000)
// grid (313 pos-tiles of 256, 2 co-blocks of 64), block 256.
// ---------------------------------------------------------------------------
__global__ void __launch_bounds__(256) proj_kernel(const float* __restrict__ w,
                                                   const float* __restrict__ bias,
                                                   float* __restrict__ out) {
    __shared__ float Ws[32 * 72];
    __shared__ float Xs[32 * 260];
    const int NP = 2 * HWSZ;
    const int tid = threadIdx.x;
    const int p0 = blockIdx.x * 256;
    const int o0 = blockIdx.y * 64;
    const float* Q = g_tmp2;
    const int tx = tid & 31;
    const int ty = tid >> 5;

    unsigned long long acc[8][4];
#pragma unroll
    for (int i = 0; i < 8; i++)
#pragma unroll
        for (int j = 0; j < 4; j++) acc[i][j] = 0ull;

    for (int cc = 0; cc < CD; cc += 32) {
#pragma unroll
        for (int it = 0; it < 8; it++) {
            int idx = tid + it * 256;
            int ol = idx >> 5, c = idx & 31;
            Ws[c * 72 + ol] = w[(size_t)(o0 + ol) * CD + cc + c];
        }
#pragma unroll
        for (int it = 0; it < 32; it++) {
            int idx = tid + it * 256;
            int pl = idx >> 5, c = idx & 31;
            int gp = p0 + pl;
            Xs[c * 260 + pl] = (gp < NP) ? Q[(size_t)gp * CD + cc + c] : 0.f;
        }
        __syncthreads();
#pragma unroll 4
        for (int c = 0; c < 32; c++) {
            float4 w0 = *(const float4*)&Ws[c * 72 + ty * 8];
            float4 w1 = *(const float4*)&Ws[c * 72 + ty * 8 + 4];
            const unsigned long long* xp =
                (const unsigned long long*)&Xs[c * 260 + tx * 8];
            unsigned long long xr[4] = {xp[0], xp[1], xp[2], xp[3]};
            unsigned long long wp[8] = {pack2(w0.x), pack2(w0.y), pack2(w0.z), pack2(w0.w),
                                        pack2(w1.x), pack2(w1.y), pack2(w1.z), pack2(w1.w)};
#pragma unroll
            for (int i = 0; i < 8; i++)
#pragma unroll
                for (int j = 0; j < 4; j++)
                    fma2(acc[i][j], wp[i], xr[j]);
        }
        __syncthreads();
    }

    float bs[8];
#pragma unroll
    for (int i = 0; i < 8; i++) bs[i] = bias[o0 + ty * 8 + i];

    const int pbase = p0 + tx * 8;
    if (pbase < NP) {   // 80000 % 8 == 0 -> all-or-nothing per thread
#pragma unroll
        for (int jp = 0; jp < 4; jp++) {
#pragma unroll
            for (int half = 0; half < 2; half++) {
                int j = jp * 2 + half;
                float4 v0, v1;
                v0.x = (half ? hi32(acc[0][jp]) : lo32(acc[0][jp])) + bs[0];
                v0.y = (half ? hi32(acc[1][jp]) : lo32(acc[1][jp])) + bs[1];
                v0.z = (half ? hi32(acc[2][jp]) : lo32(acc[2][jp])) + bs[2];
                v0.w = (half ? hi32(acc[3][jp]) : lo32(acc[3][jp])) + bs[3];
                v1.x = (half ? hi32(acc[4][jp]) : lo32(acc[4][jp])) + bs[4];
                v1.y = (half ? hi32(acc[5][jp]) : lo32(acc[5][jp])) + bs[5];
                v1.z = (half ? hi32(acc[6][jp]) : lo32(acc[6][jp])) + bs[6];
                v1.w = (half ? hi32(acc[7][jp]) : lo32(acc[7][jp])) + bs[7];
                float* row = out + (size_t)(pbase + j) * CD + o0 + ty * 8;
                *(float4*)(row)     = v0;
                *(float4*)(row + 4) = v1;
            }
        }
    }
}

extern "C" void kernel_launch(void* const* d_in, const int* in_sizes, int n_in,
                              void* d_out, int out_size) {
    const float* q   = (const float*)d_in[0];
    const float* x   = (const float*)d_in[1];
    const float* kvw = (const float*)d_in[2];
    const float* pw  = (const float*)d_in[3];
    const float* pb  = (const float*)d_in[4];
    float* out = (float*)d_out;

    conv_kernel<<<dim3(157, 4, 4), 256>>>(x, kvw);
    attn_kernel<<<dim3(625, 2), 256>>>(q, /*head=*/0, /*dil=*/1, /*stage=*/0);
    attn_kernel<<<dim3(625, 2), 256>>>(q, /*head=*/1, /*dil=*/2, /*stage=*/1);
    proj_kernel<<<dim3(313, 2), 256>>>(pw, pb, out);
}

// round 5
// speedup vs baseline: 1.3142x; 1.1963x over previous
#include <cuda_runtime.h>
#include <cuda_bf16.h>
#include <cstdint>
#include <cstddef>

#define HWSZ 40000
#define CD   128

// ---- scratch (static device globals; no runtime allocation) ----
__device__ float g_kv[4UL * 256 * 40000];     // conv output [n][o][pos]
__device__ float g_tmp[2UL * 40000 * 128];    // q after head 0 (channels-last)
__device__ float g_tmp2[2UL * 40000 * 128];   // q after head 1 (channels-last)

// ===========================================================================
// HMMA GEMM building blocks (sm_80+ portable PTX: ldmatrix + mma.sync bf16)
// ===========================================================================
#define TSTRIDE 136                        // padded row stride (bf16 elems) -> 272B
#define TILE_B  (128 * TSTRIDE * 2)        // one 128x128 bf16 tile = 34816B
#define SA_HI   0
#define SA_LO   (TILE_B)
#define SB_HI   (2 * TILE_B)
#define SB_LO   (3 * TILE_B)
#define SM_TOT  (4 * TILE_B)               // 139264B dynamic smem

__device__ __forceinline__ uint32_t smem_u32(const void* p) {
    uint32_t a;
    asm("{ .reg .u64 t; cvta.to.shared.u64 t, %1; cvt.u32.u64 %0, t; }"
        : "=r"(a) : "l"(p));
    return a;
}

#define LDMX4(r, addr)                                                        \
    asm volatile("ldmatrix.sync.aligned.m8n8.x4.shared.b16 {%0,%1,%2,%3}, [%4];" \
                 : "=r"((r)[0]), "=r"((r)[1]), "=r"((r)[2]), "=r"((r)[3])     \
                 : "r"(addr))

__device__ __forceinline__ void mma16816(float* d, const uint32_t* a,
                                         uint32_t b0, uint32_t b1) {
    asm volatile(
        "mma.sync.aligned.m16n8k16.row.col.f32.bf16.bf16.f32 "
        "{%0,%1,%2,%3}, {%4,%5,%6,%7}, {%8,%9}, {%0,%1,%2,%3};"
        : "+f"(d[0]), "+f"(d[1]), "+f"(d[2]), "+f"(d[3])
        : "r"(a[0]), "r"(a[1]), "r"(a[2]), "r"(a[3]), "r"(b0), "r"(b1));
}

// fp32 row (128 contiguous) -> hi/lo bf16 rows in padded smem tiles
__device__ __forceinline__ void convert_row(const float* __restrict__ src, bool valid,
                                            char* smem, int hi_off, int lo_off, int row) {
#pragma unroll
    for (int c = 0; c < 128; c += 8) {
        float v[8];
        if (valid) {
            float4 f0 = *(const float4*)(src + c);
            float4 f1 = *(const float4*)(src + c + 4);
            v[0] = f0.x; v[1] = f0.y; v[2] = f0.z; v[3] = f0.w;
            v[4] = f1.x; v[5] = f1.y; v[6] = f1.z; v[7] = f1.w;
        } else {
#pragma unroll
            for (int k = 0; k < 8; k++) v[k] = 0.f;
        }
        uint32_t hw[4], lw[4];
#pragma unroll
        for (int k = 0; k < 4; k++) {
            float a = v[2 * k], b = v[2 * k + 1];
            __nv_bfloat16 ha = __float2bfloat16(a), hb = __float2bfloat16(b);
            float ra = a - __bfloat162float(ha), rb = b - __bfloat162float(hb);
            __nv_bfloat16 la = __float2bfloat16(ra), lb = __float2bfloat16(rb);
            hw[k] = (uint32_t)__bfloat16_as_ushort(ha) | ((uint32_t)__bfloat16_as_ushort(hb) << 16);
            lw[k] = (uint32_t)__bfloat16_as_ushort(la) | ((uint32_t)__bfloat16_as_ushort(lb) << 16);
        }
        uint32_t off = (uint32_t)row * (TSTRIDE * 2) + (uint32_t)c * 2;
        *(uint4*)(smem + hi_off + off) = make_uint4(hw[0], hw[1], hw[2], hw[3]);
        *(uint4*)(smem + lo_off + off) = make_uint4(lw[0], lw[1], lw[2], lw[3]);
    }
}

// 3-pass split-bf16 mainloop. Warp computes 64(m) x 64(n) at (wm, wn).
// acc[mt][nt][4], mt in 0..3 (16-row tiles), nt in 0..7 (8-col tiles).
__device__ __forceinline__ void gemm_warp(uint32_t sb, int lane, int wm, int wn,
                                          float acc[4][8][4]) {
    const int aoff[3] = {SA_HI, SA_LO, SA_HI};
    const int boff[3] = {SB_HI, SB_HI, SB_LO};
    const int arow = wm + (lane & 15);
    const int acolb = ((lane >> 4) << 3);
    const int brow = wn + (lane & 7) + ((lane >> 4) << 3);
    const int bcolb = (((lane >> 3) & 1) << 3);
#pragma unroll
    for (int pass = 0; pass < 3; pass++) {
        uint32_t ab = sb + aoff[pass];
        uint32_t bb = sb + boff[pass];
#pragma unroll 2
        for (int ks = 0; ks < 8; ks++) {
            uint32_t a[4][4], b[4][4];
            int kc = ks * 16;
#pragma unroll
            for (int mt = 0; mt < 4; mt++)
                LDMX4(a[mt], ab + (uint32_t)(arow + mt * 16) * (TSTRIDE * 2)
                               + (uint32_t)(kc + acolb) * 2);
#pragma unroll
            for (int np = 0; np < 4; np++)
                LDMX4(b[np], bb + (uint32_t)(brow + np * 16) * (TSTRIDE * 2)
                               + (uint32_t)(kc + bcolb) * 2);
#pragma unroll
            for (int mt = 0; mt < 4; mt++)
#pragma unroll
                for (int nt = 0; nt < 8; nt++)
                    mma16816(acc[mt][nt], a[mt],
                             b[nt >> 1][(nt & 1) * 2], b[nt >> 1][(nt & 1) * 2 + 1]);
        }
    }
}

// ---------------------------------------------------------------------------
// conv 1x1: g_kv[n][o][p] = sum_c W[o][c] * X[n][p][c]
// A = W rows (m=o), B = X rows (n=p). grid (313 p-tiles, 2 o, 4 n), 128 thr.
// ---------------------------------------------------------------------------
__global__ void __launch_bounds__(128, 1)
conv_hmma_kernel(const float* __restrict__ x, const float* __restrict__ w) {
    extern __shared__ char sm[];
    uint32_t sb = smem_u32(sm);
    const int tid = threadIdx.x, wid = tid >> 5, lane = tid & 31;
    const int p0 = blockIdx.x * 128;
    const int o0 = blockIdx.y * 128;
    const int n  = blockIdx.z;

    convert_row(w + (size_t)(o0 + tid) * CD, true, sm, SA_HI, SA_LO, tid);
    {
        int p = p0 + tid;
        convert_row(x + ((size_t)n * HWSZ + p) * CD, p < HWSZ, sm, SB_HI, SB_LO, tid);
    }
    __syncthreads();

    const int wm = (wid >> 1) * 64, wn = (wid & 1) * 64;
    float acc[4][8][4];
#pragma unroll
    for (int i = 0; i < 4; i++)
#pragma unroll
        for (int j = 0; j < 8; j++)
#pragma unroll
            for (int k = 0; k < 4; k++) acc[i][j][k] = 0.f;

    gemm_warp(sb, lane, wm, wn, acc);

    // epilogue: row = o, col = p
    const int g = lane >> 2, tg = lane & 3;
    float* O = g_kv + (size_t)n * 256 * HWSZ;
#pragma unroll
    for (int mt = 0; mt < 4; mt++) {
        int r = o0 + wm + mt * 16 + g;
#pragma unroll
        for (int nt = 0; nt < 8; nt++) {
            int p = p0 + wn + nt * 8 + tg * 2;
            if (p < HWSZ) {
                *(float2*)&O[(size_t)r * HWSZ + p] =
                    make_float2(acc[mt][nt][0], acc[mt][nt][1]);
                *(float2*)&O[(size_t)(r + 8) * HWSZ + p] =
                    make_float2(acc[mt][nt][2], acc[mt][nt][3]);
            }
        }
    }
}

// ---------------------------------------------------------------------------
// projection: out[p][co] = sum_c q2[p][c] * Wp[co][c] + bias[co]
// A = q2 rows (m=p), B = Wp rows (n=co). grid (625 p-tiles), 128 thr.
// ---------------------------------------------------------------------------
__global__ void __launch_bounds__(128, 1)
proj_hmma_kernel(const float* __restrict__ w, const float* __restrict__ bias,
                 float* __restrict__ out) {
    extern __shared__ char sm[];
    uint32_t sb = smem_u32(sm);
    const int tid = threadIdx.x, wid = tid >> 5, lane = tid & 31;
    const int p0 = blockIdx.x * 128;

    convert_row(g_tmp2 + (size_t)(p0 + tid) * CD, true, sm, SA_HI, SA_LO, tid);
    convert_row(w + (size_t)tid * CD, true, sm, SB_HI, SB_LO, tid);
    __syncthreads();

    const int wm = (wid >> 1) * 64, wn = (wid & 1) * 64;
    float acc[4][8][4];
#pragma unroll
    for (int i = 0; i < 4; i++)
#pragma unroll
        for (int j = 0; j < 8; j++)
#pragma unroll
            for (int k = 0; k < 4; k++) acc[i][j][k] = 0.f;

    gemm_warp(sb, lane, wm, wn, acc);

    const int g = lane >> 2, tg = lane & 3;
#pragma unroll
    for (int mt = 0; mt < 4; mt++) {
        int p = p0 + wm + mt * 16 + g;
#pragma unroll
        for (int nt = 0; nt < 8; nt++) {
            int co = wn + nt * 8 + tg * 2;
            float b0 = bias[co], b1 = bias[co + 1];
            *(float2*)&out[(size_t)p * CD + co] =
                make_float2(acc[mt][nt][0] + b0, acc[mt][nt][1] + b1);
            *(float2*)&out[(size_t)(p + 8) * CD + co] =
                make_float2(acc[mt][nt][2] + b0, acc[mt][nt][3] + b1);
        }
    }
}

// ---------------------------------------------------------------------------
// Dilate attention (unchanged; passing since round 2)
// ---------------------------------------------------------------------------
__global__ void __launch_bounds__(256, 2) attn_kernel(const float* __restrict__ qext,
                                                      int head, int dil, int stage) {
    __shared__ int2  tab[1800];
    __shared__ float st[64 * 129];
    const int tid = threadIdx.x;

    for (int m = tid; m < 1800; m += 256) {
        int c200 = m / 9;
        int kk = m - c200 * 9;
        int i = kk / 3;
        int j = kk - i * 3;
        int di = (i - 1) * dil;
        int dj = (j - 1) * dil;
        tab[m] = make_int2(c200 * 25600 + di * 128 + dj, (di << 16) | (dj & 0xFFFF));
    }
    __syncthreads();

    const float* qin = stage ? g_tmp : qext;
    float* qout      = stage ? g_tmp2 : g_tmp;

    const int b   = blockIdx.y;
    const int pl  = tid & 63;
    const int nh  = tid >> 6;
    const int pos0 = blockIdx.x * 64;
    const int pos  = pos0 + pl;

    const float* Qf = qin + (size_t)b * HWSZ * CD;
    const float* Kb = g_kv + ((size_t)(2 * b) * 256 + head * 128) * HWSZ;
    const float* Vb = g_kv + ((size_t)(2 * b + 1) * 256 + head * 128) * HWSZ;

    const int G0 = nh * 288 * 40000 + pos;
    const int m0 = G0 / 25600;
    const int l0 = G0 - m0 * 25600;

    float sc[9];
#pragma unroll
    for (int k = 0; k < 9; k++) sc[k] = 0.f;

    int M = m0, L = l0;
#pragma unroll 1
    for (int hd = 0; hd < 32; hd++) {
        float qv = Qf[(size_t)(nh * 32 + hd) * HWSZ + pos];
#pragma unroll
        for (int kk = 0; kk < 9; kk++) {
            int2 t = tab[M];
            int lw = L >> 7, lc = L & 127;
            int di = t.y >> 16;
            int dj = (int)(short)(t.y & 0xFFFF);
            bool ok = ((unsigned)(lw + di) < 200u) && ((unsigned)(lc + dj) < 128u);
            float kv = ok ? __ldg(&Kb[t.x + L]) : 0.f;
            sc[kk] = fmaf(qv, kv, sc[kk]);
            M += 1; L += 14400;
            if (L >= 25600) { L -= 25600; M += 1; }
        }
    }

    const float SCALE = 0.17677669529663687f;
    float mx = -1e30f;
#pragma unroll
    for (int k = 0; k < 9; k++) { sc[k] *= SCALE; mx = fmaxf(mx, sc[k]); }
    float sum = 0.f;
#pragma unroll
    for (int k = 0; k < 9; k++) { sc[k] = __expf(sc[k] - mx); sum += sc[k]; }
    float inv = 1.0f / sum;
#pragma unroll
    for (int k = 0; k < 9; k++) sc[k] *= inv;

    M = m0; L = l0;
#pragma unroll 1
    for (int hd = 0; hd < 32; hd++) {
        float o = 0.f;
#pragma unroll
        for (int kk = 0; kk < 9; kk++) {
            int2 t = tab[M];
            int lw = L >> 7, lc = L & 127;
            int di = t.y >> 16;
            int dj = (int)(short)(t.y & 0xFFFF);
            bool ok = ((unsigned)(lw + di) < 200u) && ((unsigned)(lc + dj) < 128u);
            float vv = ok ? __ldg(&Vb[t.x + L]) : 0.f;
            o = fmaf(sc[kk], vv, o);
            M += 1; L += 14400;
            if (L >= 25600) { L -= 25600; M += 1; }
        }
        st[pl * 129 + nh * 32 + hd] = o;
    }
    __syncthreads();

    float* Ob = qout + (size_t)b * HWSZ * CD + (size_t)pos0 * CD;
#pragma unroll
    for (int it = 0; it < 32; it++) {
        int f = tid + it * 256;
        int p = f >> 7, c = f & 127;
        Ob[f] = st[p * 129 + c];
    }
}

extern "C" void kernel_launch(void* const* d_in, const int* in_sizes, int n_in,
                              void* d_out, int out_size) {
    const float* q   = (const float*)d_in[0];
    const float* x   = (const float*)d_in[1];
    const float* kvw = (const float*)d_in[2];
    const float* pw  = (const float*)d_in[3];
    const float* pb  = (const float*)d_in[4];
    float* out = (float*)d_out;

    cudaFuncSetAttribute(conv_hmma_kernel, cudaFuncAttributeMaxDynamicSharedMemorySize, SM_TOT);
    cudaFuncSetAttribute(proj_hmma_kernel, cudaFuncAttributeMaxDynamicSharedMemorySize, SM_TOT);

    conv_hmma_kernel<<<dim3(313, 2, 4), 128, SM_TOT>>>(x, kvw);
    attn_kernel<<<dim3(625, 2), 256>>>(q, /*head=*/0, /*dil=*/1, /*stage=*/0);
    attn_kernel<<<dim3(625, 2), 256>>>(q, /*head=*/1, /*dil=*/2, /*stage=*/1);
    proj_hmma_kernel<<<625, 128, SM_TOT>>>(pw, pb, out);
}

// round 6
// speedup vs baseline: 1.8543x; 1.4109x over previous
#include <cuda_runtime.h>
#include <cuda_bf16.h>
#include <cstdint>
#include <cstddef>

#define HWSZ 40000
#define CD   128

// ---- scratch (static device globals; no runtime allocation) ----
__device__ float g_kv[4UL * 256 * 40000];     // conv output [n][o][pos]
__device__ float g_tmp[2UL * 40000 * 128];    // q after head 0 (channels-last)
__device__ float g_tmp2[2UL * 40000 * 128];   // q after head 1 (channels-last)

// ===========================================================================
// HMMA GEMM building blocks (sm_80+ portable PTX: ldmatrix + mma.sync bf16)
// K processed in 2 chunks of 64 -> 4 tiles of 128x72 bf16 = 73728B smem
// ===========================================================================
#define RS      72                          // padded row stride (bf16) -> 144B
#define TILE_B  (128 * RS * 2)              // 18432B
#define SA_HI   0
#define SA_LO   (TILE_B)
#define SB_HI   (2 * TILE_B)
#define SB_LO   (3 * TILE_B)
#define SM_TOT  (4 * TILE_B)                // 73728B dynamic smem

__device__ __forceinline__ uint32_t smem_u32(const void* p) {
    uint32_t a;
    asm("{ .reg .u64 t; cvta.to.shared.u64 t, %1; cvt.u32.u64 %0, t; }"
        : "=r"(a) : "l"(p));
    return a;
}

#define LDMX4(r, addr)                                                        \
    asm volatile("ldmatrix.sync.aligned.m8n8.x4.shared.b16 {%0,%1,%2,%3}, [%4];" \
                 : "=r"((r)[0]), "=r"((r)[1]), "=r"((r)[2]), "=r"((r)[3])     \
                 : "r"(addr))

__device__ __forceinline__ void mma16816(float* d, const uint32_t* a,
                                         uint32_t b0, uint32_t b1) {
    asm volatile(
        "mma.sync.aligned.m16n8k16.row.col.f32.bf16.bf16.f32 "
        "{%0,%1,%2,%3}, {%4,%5,%6,%7}, {%8,%9}, {%0,%1,%2,%3};"
        : "+f"(d[0]), "+f"(d[1]), "+f"(d[2]), "+f"(d[3])
        : "r"(a[0]), "r"(a[1]), "r"(a[2]), "r"(a[3]), "r"(b0), "r"(b1));
}

// 32 fp32 values -> hi/lo bf16 at smem row `row`, chunk-local cols [c0,c0+32)
__device__ __forceinline__ void convert32(const float* __restrict__ src, bool valid,
                                          char* smem, int hi_off, int lo_off,
                                          int row, int c0) {
#pragma unroll
    for (int c = 0; c < 32; c += 8) {
        float v[8];
        if (valid) {
            float4 f0 = *(const float4*)(src + c);
            float4 f1 = *(const float4*)(src + c + 4);
            v[0] = f0.x; v[1] = f0.y; v[2] = f0.z; v[3] = f0.w;
            v[4] = f1.x; v[5] = f1.y; v[6] = f1.z; v[7] = f1.w;
        } else {
#pragma unroll
            for (int k = 0; k < 8; k++) v[k] = 0.f;
        }
        uint32_t hw[4], lw[4];
#pragma unroll
        for (int k = 0; k < 4; k++) {
            float a = v[2 * k], b = v[2 * k + 1];
            __nv_bfloat16 ha = __float2bfloat16(a), hb = __float2bfloat16(b);
            float ra = a - __bfloat162float(ha), rb = b - __bfloat162float(hb);
            __nv_bfloat16 la = __float2bfloat16(ra), lb = __float2bfloat16(rb);
            hw[k] = (uint32_t)__bfloat16_as_ushort(ha) | ((uint32_t)__bfloat16_as_ushort(hb) << 16);
            lw[k] = (uint32_t)__bfloat16_as_ushort(la) | ((uint32_t)__bfloat16_as_ushort(lb) << 16);
        }
        uint32_t off = (uint32_t)row * (RS * 2) + (uint32_t)(c0 + c) * 2;
        *(uint4*)(smem + hi_off + off) = make_uint4(hw[0], hw[1], hw[2], hw[3]);
        *(uint4*)(smem + lo_off + off) = make_uint4(lw[0], lw[1], lw[2], lw[3]);
    }
}

// one 64-wide K-chunk, 3-pass split-bf16. Warp tile 64(m) x 32(n) at (wm, wn).
__device__ __forceinline__ void gemm_chunk(uint32_t sb, int lane, int wm, int wn,
                                           float acc[4][4][4]) {
    const int aoff[3] = {SA_HI, SA_LO, SA_HI};
    const int boff[3] = {SB_HI, SB_HI, SB_LO};
    const int arow  = wm + (lane & 15);
    const int acolb = ((lane >> 4) << 3);
    const int brow  = wn + (lane & 7) + ((lane >> 4) << 3);
    const int bcolb = (((lane >> 3) & 1) << 3);
#pragma unroll
    for (int pass = 0; pass < 3; pass++) {
        uint32_t ab = sb + aoff[pass];
        uint32_t bb = sb + boff[pass];
#pragma unroll
        for (int ks = 0; ks < 4; ks++) {
            uint32_t a[4][4], b[2][4];
            int kc = ks * 16;
#pragma unroll
            for (int mt = 0; mt < 4; mt++)
                LDMX4(a[mt], ab + (uint32_t)(arow + mt * 16) * (RS * 2)
                               + (uint32_t)(kc + acolb) * 2);
#pragma unroll
            for (int np = 0; np < 2; np++)
                LDMX4(b[np], bb + (uint32_t)(brow + np * 16) * (RS * 2)
                               + (uint32_t)(kc + bcolb) * 2);
#pragma unroll
            for (int mt = 0; mt < 4; mt++)
#pragma unroll
                for (int nt = 0; nt < 4; nt++)
                    mma16816(acc[mt][nt], a[mt],
                             b[nt >> 1][(nt & 1) * 2], b[nt >> 1][(nt & 1) * 2 + 1]);
        }
    }
}

// ---------------------------------------------------------------------------
// conv 1x1: g_kv[n][o][p] = sum_c W[o][c] * X[n][p][c]
// A = W rows (m=o), B = X rows (n=p). grid (313 p-tiles, 2 o, 4 n), 256 thr.
// ---------------------------------------------------------------------------
__global__ void __launch_bounds__(256)
conv_hmma_kernel(const float* __restrict__ x, const float* __restrict__ w) {
    extern __shared__ char sm[];
    uint32_t sb = smem_u32(sm);
    const int tid = threadIdx.x, wid = tid >> 5, lane = tid & 31;
    const int p0 = blockIdx.x * 128;
    const int o0 = blockIdx.y * 128;
    const int n  = blockIdx.z;

    const int wm = (wid & 1) * 64, wn = (wid >> 1) * 32;
    float acc[4][4][4];
#pragma unroll
    for (int i = 0; i < 4; i++)
#pragma unroll
        for (int j = 0; j < 4; j++)
#pragma unroll
            for (int k = 0; k < 4; k++) acc[i][j][k] = 0.f;

    const int r  = tid >> 1;
    const int c0 = (tid & 1) * 32;
    const int p  = p0 + r;
#pragma unroll
    for (int kc = 0; kc < 128; kc += 64) {
        convert32(w + (size_t)(o0 + r) * CD + kc + c0, true, sm, SA_HI, SA_LO, r, c0);
        convert32(x + ((size_t)n * HWSZ + p) * CD + kc + c0, p < HWSZ,
                  sm, SB_HI, SB_LO, r, c0);
        __syncthreads();
        gemm_chunk(sb, lane, wm, wn, acc);
        __syncthreads();
    }

    const int g = lane >> 2, tg = lane & 3;
    float* O = g_kv + (size_t)n * 256 * HWSZ;
#pragma unroll
    for (int mt = 0; mt < 4; mt++) {
        int rr = o0 + wm + mt * 16 + g;
#pragma unroll
        for (int nt = 0; nt < 4; nt++) {
            int pp = p0 + wn + nt * 8 + tg * 2;
            if (pp < HWSZ) {
                *(float2*)&O[(size_t)rr * HWSZ + pp] =
                    make_float2(acc[mt][nt][0], acc[mt][nt][1]);
                *(float2*)&O[(size_t)(rr + 8) * HWSZ + pp] =
                    make_float2(acc[mt][nt][2], acc[mt][nt][3]);
            }
        }
    }
}

// ---------------------------------------------------------------------------
// projection: out[p][co] = sum_c q2[p][c] * Wp[co][c] + bias[co]
// A = q2 rows (m=p), B = Wp rows (n=co). grid (625 p-tiles), 256 thr.
// ---------------------------------------------------------------------------
__global__ void __launch_bounds__(256)
proj_hmma_kernel(const float* __restrict__ w, const float* __restrict__ bias,
                 float* __restrict__ out) {
    extern __shared__ char sm[];
    uint32_t sb = smem_u32(sm);
    const int tid = threadIdx.x, wid = tid >> 5, lane = tid & 31;
    const int p0 = blockIdx.x * 128;

    const int wm = (wid & 1) * 64, wn = (wid >> 1) * 32;
    float acc[4][4][4];
#pragma unroll
    for (int i = 0; i < 4; i++)
#pragma unroll
        for (int j = 0; j < 4; j++)
#pragma unroll
            for (int k = 0; k < 4; k++) acc[i][j][k] = 0.f;

    const int r  = tid >> 1;
    const int c0 = (tid & 1) * 32;
#pragma unroll
    for (int kc = 0; kc < 128; kc += 64) {
        convert32(g_tmp2 + (size_t)(p0 + r) * CD + kc + c0, true, sm, SA_HI, SA_LO, r, c0);
        convert32(w + (size_t)r * CD + kc + c0, true, sm, SB_HI, SB_LO, r, c0);
        __syncthreads();
        gemm_chunk(sb, lane, wm, wn, acc);
        __syncthreads();
    }

    const int g = lane >> 2, tg = lane & 3;
#pragma unroll
    for (int mt = 0; mt < 4; mt++) {
        int p = p0 + wm + mt * 16 + g;
#pragma unroll
        for (int nt = 0; nt < 4; nt++) {
            int co = wn + nt * 8 + tg * 2;
            float b0 = bias[co], b1 = bias[co + 1];
            *(float2*)&out[(size_t)p * CD + co] =
                make_float2(acc[mt][nt][0] + b0, acc[mt][nt][1] + b1);
            *(float2*)&out[(size_t)(p + 8) * CD + co] =
                make_float2(acc[mt][nt][2] + b0, acc[mt][nt][3] + b1);
        }
    }
}

// ---------------------------------------------------------------------------
// Dilate attention, channel-paired: channels hd and hd+16 share the exact
// (M, L, mask, di, dj) stream; second gather = first address + 640000 elems
// (step offset 144 -> M+225 = +25 super-rows, L unchanged, kk unchanged).
// ---------------------------------------------------------------------------
__global__ void __launch_bounds__(256, 2) attn_kernel(const float* __restrict__ qext,
                                                      int head, int dil, int stage) {
    __shared__ int2  tab[1800];
    __shared__ float st[64 * 129];
    const int tid = threadIdx.x;

    for (int m = tid; m < 1800; m += 256) {
        int c200 = m / 9;
        int kk = m - c200 * 9;
        int i = kk / 3;
        int j = kk - i * 3;
        int di = (i - 1) * dil;
        int dj = (j - 1) * dil;
        tab[m] = make_int2(c200 * 25600 + di * 128 + dj, (di << 16) | (dj & 0xFFFF));
    }
    __syncthreads();

    const float* qin = stage ? g_tmp : qext;
    float* qout      = stage ? g_tmp2 : g_tmp;

    const int b   = blockIdx.y;
    const int pl  = tid & 63;
    const int nh  = tid >> 6;
    const int pos0 = blockIdx.x * 64;
    const int pos  = pos0 + pl;

    const float* Qf = qin + (size_t)b * HWSZ * CD;
    const float* Kb = g_kv + ((size_t)(2 * b) * 256 + head * 128) * HWSZ;
    const float* Vb = g_kv + ((size_t)(2 * b + 1) * 256 + head * 128) * HWSZ;

    const int G0 = nh * 288 * 40000 + pos;
    const int m0 = G0 / 25600;
    const int l0 = G0 - m0 * 25600;

    // ---- pass 1: scores (channels hd and hd+16 per iteration) ----
    float sc[9];
#pragma unroll
    for (int k = 0; k < 9; k++) sc[k] = 0.f;

    int M = m0, L = l0;
#pragma unroll 1
    for (int hd = 0; hd < 16; hd++) {
        float q1 = Qf[(size_t)(nh * 32 + hd) * HWSZ + pos];
        float q2 = Qf[(size_t)(nh * 32 + hd + 16) * HWSZ + pos];
#pragma unroll
        for (int kk = 0; kk < 9; kk++) {
            int2 t = tab[M];
            int lw = L >> 7, lc = L & 127;
            int di = t.y >> 16;
            int dj = (int)(short)(t.y & 0xFFFF);
            bool ok = ((unsigned)(lw + di) < 200u) && ((unsigned)(lc + dj) < 128u);
            int a = t.x + L;
            float k1 = ok ? __ldg(&Kb[a]) : 0.f;
            float k2 = ok ? __ldg(&Kb[a + 640000]) : 0.f;
            sc[kk] = fmaf(q1, k1, sc[kk]);
            sc[kk] = fmaf(q2, k2, sc[kk]);
            M += 1; L += 14400;
            if (L >= 25600) { L -= 25600; M += 1; }
        }
    }

    // ---- softmax over 9 ----
    const float SCALE = 0.17677669529663687f;   // 32^-0.5
    float mx = -1e30f;
#pragma unroll
    for (int k = 0; k < 9; k++) { sc[k] *= SCALE; mx = fmaxf(mx, sc[k]); }
    float sum = 0.f;
#pragma unroll
    for (int k = 0; k < 9; k++) { sc[k] = __expf(sc[k] - mx); sum += sc[k]; }
    float inv = 1.0f / sum;
#pragma unroll
    for (int k = 0; k < 9; k++) sc[k] *= inv;

    // ---- pass 2: outputs ----
    M = m0; L = l0;
#pragma unroll 1
    for (int hd = 0; hd < 16; hd++) {
        float o1 = 0.f, o2 = 0.f;
#pragma unroll
        for (int kk = 0; kk < 9; kk++) {
            int2 t = tab[M];
            int lw = L >> 7, lc = L & 127;
            int di = t.y >> 16;
            int dj = (int)(short)(t.y & 0xFFFF);
            bool ok = ((unsigned)(lw + di) < 200u) && ((unsigned)(lc + dj) < 128u);
            int a = t.x + L;
            float v1 = ok ? __ldg(&Vb[a]) : 0.f;
            float v2 = ok ? __ldg(&Vb[a + 640000]) : 0.f;
            o1 = fmaf(sc[kk], v1, o1);
            o2 = fmaf(sc[kk], v2, o2);
            M += 1; L += 14400;
            if (L >= 25600) { L -= 25600; M += 1; }
        }
        st[pl * 129 + nh * 32 + hd]      = o1;
        st[pl * 129 + nh * 32 + hd + 16] = o2;
    }
    __syncthreads();

    // coalesced channels-last writeback: 64 pos x 128 ch contiguous
    float* Ob = qout + (size_t)b * HWSZ * CD + (size_t)pos0 * CD;
#pragma unroll
    for (int it = 0; it < 32; it++) {
        int f = tid + it * 256;
        int p = f >> 7, c = f & 127;
        Ob[f] = st[p * 129 + c];
    }
}

extern "C" void kernel_launch(void* const* d_in, const int* in_sizes, int n_in,
                              void* d_out, int out_size) {
    const float* q   = (const float*)d_in[0];
    const float* x   = (const float*)d_in[1];
    const float* kvw = (const float*)d_in[2];
    const float* pw  = (const float*)d_in[3];
    const float* pb  = (const float*)d_in[4];
    float* out = (float*)d_out;

    cudaFuncSetAttribute(conv_hmma_kernel, cudaFuncAttributeMaxDynamicSharedMemorySize, SM_TOT);
    cudaFuncSetAttribute(proj_hmma_kernel, cudaFuncAttributeMaxDynamicSharedMemorySize, SM_TOT);

    conv_hmma_kernel<<<dim3(313, 2, 4), 256, SM_TOT>>>(x, kvw);
    attn_kernel<<<dim3(625, 2), 256>>>(q, /*head=*/0, /*dil=*/1, /*stage=*/0);
    attn_kernel<<<dim3(625, 2), 256>>>(q, /*head=*/1, /*dil=*/2, /*stage=*/1);
    proj_hmma_kernel<<<625, 256, SM_TOT>>>(pw, pb, out);
}

// round 9
// speedup vs baseline: 1.9884x; 1.0723x over previous
#include <cuda_runtime.h>
#include <cuda_bf16.h>
#include <cstdint>
#include <cstddef>

#define HWSZ 40000
#define CD   128

// ---- scratch (static device globals; no runtime allocation) ----
// NOTE: these symbols are ONLY referenced from device code (host-side kernel
// args of __device__ symbols give host-shadow addresses — the round-7/8 bug).
__device__ float g_kv[4UL * 256 * 40000];        // conv output [n][o][pos] fp32
__device__ float g_tmp[2UL * 40000 * 128];       // q after head 0 (channels-last fp32)
__device__ __align__(16) __nv_bfloat16 g_xhi[4UL * 40000 * 128];   // X split-bf16
__device__ __align__(16) __nv_bfloat16 g_xlo[4UL * 40000 * 128];
__device__ __align__(16) __nv_bfloat16 g_whi[256 * 128];           // conv weight split
__device__ __align__(16) __nv_bfloat16 g_wlo[256 * 128];
__device__ __align__(16) __nv_bfloat16 g_pwhi[128 * 128];          // proj weight split
__device__ __align__(16) __nv_bfloat16 g_pwlo[128 * 128];
__device__ __align__(16) __nv_bfloat16 g_q2hi[2UL * 40000 * 128];  // q after head 1, split
__device__ __align__(16) __nv_bfloat16 g_q2lo[2UL * 40000 * 128];

// ===========================================================================
// PTX helpers
// ===========================================================================
__device__ __forceinline__ uint32_t smem_u32(const void* p) {
    uint32_t a;
    asm("{ .reg .u64 t; cvta.to.shared.u64 t, %1; cvt.u32.u64 %0, t; }"
        : "=r"(a) : "l"(p));
    return a;
}
#define LDMX4(r, addr)                                                        \
    asm volatile("ldmatrix.sync.aligned.m8n8.x4.shared.b16 {%0,%1,%2,%3}, [%4];" \
                 : "=r"((r)[0]), "=r"((r)[1]), "=r"((r)[2]), "=r"((r)[3])     \
                 : "r"(addr))
__device__ __forceinline__ void mma16816(float* d, const uint32_t* a,
                                         uint32_t b0, uint32_t b1) {
    asm volatile(
        "mma.sync.aligned.m16n8k16.row.col.f32.bf16.bf16.f32 "
        "{%0,%1,%2,%3}, {%4,%5,%6,%7}, {%8,%9}, {%0,%1,%2,%3};"
        : "+f"(d[0]), "+f"(d[1]), "+f"(d[2]), "+f"(d[3])
        : "r"(a[0]), "r"(a[1]), "r"(a[2]), "r"(a[3]), "r"(b0), "r"(b1));
}
#define CPA16(dst, src) \
    asm volatile("cp.async.cg.shared.global [%0], [%1], 16;" :: "r"(dst), "l"(src) : "memory")
#define CPA16Z(dst, src, sz) \
    asm volatile("cp.async.cg.shared.global [%0], [%1], 16, %2;" :: "r"(dst), "l"(src), "r"(sz) : "memory")
#define CPA_COMMIT() asm volatile("cp.async.commit_group;" ::: "memory")
#define CPA_WAIT0()  asm volatile("cp.async.wait_group 0;" ::: "memory")

// ===========================================================================
// split-bf16 conversion pre-pass. Destinations bound IN DEVICE CODE.
// ===========================================================================
__device__ __forceinline__ void split4(float4 v, uint2& hw, uint2& lw) {
    float f[4] = {v.x, v.y, v.z, v.w};
    uint32_t h2[2] = {0, 0}, l2[2] = {0, 0};
#pragma unroll
    for (int k = 0; k < 4; k++) {
        __nv_bfloat16 h = __float2bfloat16(f[k]);
        __nv_bfloat16 l = __float2bfloat16(f[k] - __bfloat162float(h));
        h2[k >> 1] |= (uint32_t)__bfloat16_as_ushort(h) << ((k & 1) * 16);
        l2[k >> 1] |= (uint32_t)__bfloat16_as_ushort(l) << ((k & 1) * 16);
    }
    hw = make_uint2(h2[0], h2[1]);
    lw = make_uint2(l2[0], l2[1]);
}

__global__ void __launch_bounds__(256) cvt_x_kernel(const float* __restrict__ x) {
    int i = blockIdx.x * blockDim.x + threadIdx.x;   // over 5,120,000 float4
    if (i >= 5120000) return;
    uint2 hw, lw;
    split4(((const float4*)x)[i], hw, lw);
    ((uint2*)g_xhi)[i] = hw;
    ((uint2*)g_xlo)[i] = lw;
}

__global__ void __launch_bounds__(256) cvt_w_kernel(const float* __restrict__ kvw,
                                                    const float* __restrict__ pw) {
    int i = blockIdx.x * blockDim.x + threadIdx.x;   // 8192 kvw + 4096 pw float4
    uint2 hw, lw;
    if (i < 8192) {
        split4(((const float4*)kvw)[i], hw, lw);
        ((uint2*)g_whi)[i] = hw;
        ((uint2*)g_wlo)[i] = lw;
    } else if (i < 12288) {
        int j = i - 8192;
        split4(((const float4*)pw)[j], hw, lw);
        ((uint2*)g_pwhi)[j] = hw;
        ((uint2*)g_pwlo)[j] = lw;
    }
}

// ===========================================================================
// GEMM tile layout: 128 rows x 128 bf16 cols, padded rows of 272B (136 elems).
// 272 mod 128 = 16 -> consecutive rows shift 4 banks: ldmatrix conflict-free.
// Reader formulas are the round-6-proven gemm_chunk with RS=136, ks<8.
// ===========================================================================
#define RSB  272                     // row stride bytes
#define TLB  (128 * RSB)             // one tile = 34816B
#define A_HI 0
#define A_LO (TLB)
#define B_HI (2 * TLB)
#define B_LO (3 * TLB)
#define SMT  (4 * TLB)               // 139264B dynamic smem

__device__ __forceinline__ void gemm128(uint32_t sb, int lane, int wm, int wn,
                                        float acc[4][4][4]) {
    const int aoff[3] = {A_HI, A_LO, A_HI};
    const int boff[3] = {B_HI, B_HI, B_LO};
    const int arow  = wm + (lane & 15);
    const int acolb = ((lane >> 4) << 3);
    const int brow  = wn + (lane & 7) + ((lane >> 4) << 3);
    const int bcolb = (((lane >> 3) & 1) << 3);
#pragma unroll
    for (int pass = 0; pass < 3; pass++) {
        uint32_t ab = sb + aoff[pass];
        uint32_t bb = sb + boff[pass];
#pragma unroll
        for (int ks = 0; ks < 8; ks++) {
            uint32_t a[4][4], b[2][4];
            int kc = ks * 16;
#pragma unroll
            for (int mt = 0; mt < 4; mt++)
                LDMX4(a[mt], ab + (uint32_t)(arow + mt * 16) * RSB
                               + (uint32_t)(kc + acolb) * 2);
#pragma unroll
            for (int np = 0; np < 2; np++)
                LDMX4(b[np], bb + (uint32_t)(brow + np * 16) * RSB
                               + (uint32_t)(kc + bcolb) * 2);
#pragma unroll
            for (int mt = 0; mt < 4; mt++)
#pragma unroll
                for (int nt = 0; nt < 4; nt++)
                    mma16816(acc[mt][nt], a[mt],
                             b[nt >> 1][(nt & 1) * 2], b[nt >> 1][(nt & 1) * 2 + 1]);
        }
    }
}

// ---------------------------------------------------------------------------
// conv 1x1: g_kv[n][o][p] = sum_c W[o][c] * X[n][p][c]
// grid (313 p-tiles, 2 o-blocks of 128, 4 n), 256 threads (8 warps: 2m x 4n).
// ---------------------------------------------------------------------------
__global__ void __launch_bounds__(256, 1) conv_hmma_kernel() {
    extern __shared__ char sm[];
    uint32_t sb = smem_u32(sm);
    const int tid = threadIdx.x, wid = tid >> 5, lane = tid & 31;
    const int p0 = blockIdx.x * 128;
    const int o0 = blockIdx.y * 128;
    const int n  = blockIdx.z;

    // A = W rows [o0, o0+128): 128 rows x 16 segs x 2 (hi/lo) = 4096 segs
#pragma unroll
    for (int i = 0; i < 16; i++) {
        int idx = tid + i * 256;
        int c16 = idx & 15, row = (idx >> 4) & 127, hl = idx >> 11;
        const __nv_bfloat16* src = (hl ? g_wlo : g_whi)
                                 + (size_t)(o0 + row) * CD + c16 * 8;
        uint32_t dst = sb + (hl ? A_LO : A_HI) + (uint32_t)row * RSB
                     + (uint32_t)c16 * 16;
        CPA16(dst, src);
    }
    // B = X rows [p0, p0+128), zero-filled past HWSZ
    const size_t xoff = (size_t)n * HWSZ * CD;
#pragma unroll
    for (int i = 0; i < 16; i++) {
        int idx = tid + i * 256;
        int c16 = idx & 15, row = (idx >> 4) & 127, hl = idx >> 11;
        int p = p0 + row;
        int sz = (p < HWSZ) ? 16 : 0;
        int pc = (p < HWSZ) ? p : 0;
        const __nv_bfloat16* src = (hl ? g_xlo : g_xhi)
                                 + xoff + (size_t)pc * CD + c16 * 8;
        uint32_t dst = sb + (hl ? B_LO : B_HI) + (uint32_t)row * RSB
                     + (uint32_t)c16 * 16;
        CPA16Z(dst, src, sz);
    }
    CPA_COMMIT();

    const int wm = (wid & 1) * 64, wn = (wid >> 1) * 32;
    float acc[4][4][4];
#pragma unroll
    for (int i = 0; i < 4; i++)
#pragma unroll
        for (int j = 0; j < 4; j++)
#pragma unroll
            for (int k = 0; k < 4; k++) acc[i][j][k] = 0.f;

    CPA_WAIT0();
    __syncthreads();
    gemm128(sb, lane, wm, wn, acc);

    const int g = lane >> 2, tg = lane & 3;
    float* O = g_kv + (size_t)n * 256 * HWSZ;
#pragma unroll
    for (int mt = 0; mt < 4; mt++) {
        int rr = o0 + wm + mt * 16 + g;
#pragma unroll
        for (int nt = 0; nt < 4; nt++) {
            int pp = p0 + wn + nt * 8 + tg * 2;
            if (pp < HWSZ) {
                *(float2*)&O[(size_t)rr * HWSZ + pp] =
                    make_float2(acc[mt][nt][0], acc[mt][nt][1]);
                *(float2*)&O[(size_t)(rr + 8) * HWSZ + pp] =
                    make_float2(acc[mt][nt][2], acc[mt][nt][3]);
            }
        }
    }
}

// ---------------------------------------------------------------------------
// projection: out[p][co] = sum_c q2[p][c] * Wp[co][c] + bias[co]
// grid (625 p-tiles of 128 over 80000), 256 threads.
// ---------------------------------------------------------------------------
__global__ void __launch_bounds__(256, 1)
proj_hmma_kernel(const float* __restrict__ bias, float* __restrict__ out) {
    extern __shared__ char sm[];
    uint32_t sb = smem_u32(sm);
    const int tid = threadIdx.x, wid = tid >> 5, lane = tid & 31;
    const int p0 = blockIdx.x * 128;

    // A = q2 rows [p0, p0+128) (always in range: 625*128 == 80000)
#pragma unroll
    for (int i = 0; i < 16; i++) {
        int idx = tid + i * 256;
        int c16 = idx & 15, row = (idx >> 4) & 127, hl = idx >> 11;
        const __nv_bfloat16* src = (hl ? g_q2lo : g_q2hi)
                                 + (size_t)(p0 + row) * CD + c16 * 8;
        uint32_t dst = sb + (hl ? A_LO : A_HI) + (uint32_t)row * RSB
                     + (uint32_t)c16 * 16;
        CPA16(dst, src);
    }
    // B = Wp rows [0, 128)
#pragma unroll
    for (int i = 0; i < 16; i++) {
        int idx = tid + i * 256;
        int c16 = idx & 15, row = (idx >> 4) & 127, hl = idx >> 11;
        const __nv_bfloat16* src = (hl ? g_pwlo : g_pwhi)
                                 + (size_t)row * CD + c16 * 8;
        uint32_t dst = sb + (hl ? B_LO : B_HI) + (uint32_t)row * RSB
                     + (uint32_t)c16 * 16;
        CPA16(dst, src);
    }
    CPA_COMMIT();

    const int wm = (wid & 1) * 64, wn = (wid >> 1) * 32;
    float acc[4][4][4];
#pragma unroll
    for (int i = 0; i < 4; i++)
#pragma unroll
        for (int j = 0; j < 4; j++)
#pragma unroll
            for (int k = 0; k < 4; k++) acc[i][j][k] = 0.f;

    CPA_WAIT0();
    __syncthreads();
    gemm128(sb, lane, wm, wn, acc);

    const int g = lane >> 2, tg = lane & 3;
#pragma unroll
    for (int mt = 0; mt < 4; mt++) {
        int p = p0 + wm + mt * 16 + g;
#pragma unroll
        for (int nt = 0; nt < 4; nt++) {
            int co = wn + nt * 8 + tg * 2;
            float b0 = bias[co], b1 = bias[co + 1];
            *(float2*)&out[(size_t)p * CD + co] =
                make_float2(acc[mt][nt][0] + b0, acc[mt][nt][1] + b1);
            *(float2*)&out[(size_t)(p + 8) * CD + co] =
                make_float2(acc[mt][nt][2] + b0, acc[mt][nt][3] + b1);
        }
    }
}

// ---------------------------------------------------------------------------
// Dilate attention, channel-paired (hd, hd+16 share the index/mask stream).
// head 1 writes its output directly as split-bf16 for the projection GEMM.
// ---------------------------------------------------------------------------
__global__ void __launch_bounds__(256, 2) attn_kernel(const float* __restrict__ qext,
                                                      int head, int dil, int stage) {
    __shared__ int2  tab[1800];
    __shared__ float st[64 * 129];
    const int tid = threadIdx.x;

    for (int m = tid; m < 1800; m += 256) {
        int c200 = m / 9;
        int kk = m - c200 * 9;
        int i = kk / 3;
        int j = kk - i * 3;
        int di = (i - 1) * dil;
        int dj = (j - 1) * dil;
        tab[m] = make_int2(c200 * 25600 + di * 128 + dj, (di << 16) | (dj & 0xFFFF));
    }
    __syncthreads();

    const float* qin = stage ? g_tmp : qext;

    const int b   = blockIdx.y;
    const int pl  = tid & 63;
    const int nh  = tid >> 6;
    const int pos0 = blockIdx.x * 64;
    const int pos  = pos0 + pl;

    const float* Qf = qin + (size_t)b * HWSZ * CD;
    const float* Kb = g_kv + ((size_t)(2 * b) * 256 + head * 128) * HWSZ;
    const float* Vb = g_kv + ((size_t)(2 * b + 1) * 256 + head * 128) * HWSZ;

    const int G0 = nh * 288 * 40000 + pos;
    const int m0 = G0 / 25600;
    const int l0 = G0 - m0 * 25600;

    float sc[9];
#pragma unroll
    for (int k = 0; k < 9; k++) sc[k] = 0.f;

    int M = m0, L = l0;
#pragma unroll 1
    for (int hd = 0; hd < 16; hd++) {
        float q1 = Qf[(size_t)(nh * 32 + hd) * HWSZ + pos];
        float q2 = Qf[(size_t)(nh * 32 + hd + 16) * HWSZ + pos];
#pragma unroll
        for (int kk = 0; kk < 9; kk++) {
            int2 t = tab[M];
            int lw = L >> 7, lc = L & 127;
            int di = t.y >> 16;
            int dj = (int)(short)(t.y & 0xFFFF);
            bool ok = ((unsigned)(lw + di) < 200u) && ((unsigned)(lc + dj) < 128u);
            int a = t.x + L;
            float k1 = ok ? __ldg(&Kb[a]) : 0.f;
            float k2 = ok ? __ldg(&Kb[a + 640000]) : 0.f;
            sc[kk] = fmaf(q1, k1, sc[kk]);
            sc[kk] = fmaf(q2, k2, sc[kk]);
            M += 1; L += 14400;
            if (L >= 25600) { L -= 25600; M += 1; }
        }
    }

    const float SCALE = 0.17677669529663687f;
    float mx = -1e30f;
#pragma unroll
    for (int k = 0; k < 9; k++) { sc[k] *= SCALE; mx = fmaxf(mx, sc[k]); }
    float sum = 0.f;
#pragma unroll
    for (int k = 0; k < 9; k++) { sc[k] = __expf(sc[k] - mx); sum += sc[k]; }
    float inv = 1.0f / sum;
#pragma unroll
    for (int k = 0; k < 9; k++) sc[k] *= inv;

    M = m0; L = l0;
#pragma unroll 1
    for (int hd = 0; hd < 16; hd++) {
        float o1 = 0.f, o2 = 0.f;
#pragma unroll
        for (int kk = 0; kk < 9; kk++) {
            int2 t = tab[M];
            int lw = L >> 7, lc = L & 127;
            int di = t.y >> 16;
            int dj = (int)(short)(t.y & 0xFFFF);
            bool ok = ((unsigned)(lw + di) < 200u) && ((unsigned)(lc + dj) < 128u);
            int a = t.x + L;
            float v1 = ok ? __ldg(&Vb[a]) : 0.f;
            float v2 = ok ? __ldg(&Vb[a + 640000]) : 0.f;
            o1 = fmaf(sc[kk], v1, o1);
            o2 = fmaf(sc[kk], v2, o2);
            M += 1; L += 14400;
            if (L >= 25600) { L -= 25600; M += 1; }
        }
        st[pl * 129 + nh * 32 + hd]      = o1;
        st[pl * 129 + nh * 32 + hd + 16] = o2;
    }
    __syncthreads();

    const size_t obase = (size_t)b * HWSZ * CD + (size_t)pos0 * CD;
    if (stage) {
        __nv_bfloat16* Hh = g_q2hi + obase;
        __nv_bfloat16* Hl = g_q2lo + obase;
#pragma unroll
        for (int it = 0; it < 32; it++) {
            int f = tid + it * 256;
            int p = f >> 7, c = f & 127;
            float v = st[p * 129 + c];
            __nv_bfloat16 h = __float2bfloat16(v);
            Hh[f] = h;
            Hl[f] = __float2bfloat16(v - __bfloat162float(h));
        }
    } else {
        float* Ob = g_tmp + obase;
#pragma unroll
        for (int it = 0; it < 32; it++) {
            int f = tid + it * 256;
            int p = f >> 7, c = f & 127;
            Ob[f] = st[p * 129 + c];
        }
    }
}

extern "C" void kernel_launch(void* const* d_in, const int* in_sizes, int n_in,
                              void* d_out, int out_size) {
    const float* q   = (const float*)d_in[0];
    const float* x   = (const float*)d_in[1];
    const float* kvw = (const float*)d_in[2];
    const float* pw  = (const float*)d_in[3];
    const float* pb  = (const float*)d_in[4];
    float* out = (float*)d_out;

    cudaFuncSetAttribute(conv_hmma_kernel, cudaFuncAttributeMaxDynamicSharedMemorySize, SMT);
    cudaFuncSetAttribute(proj_hmma_kernel, cudaFuncAttributeMaxDynamicSharedMemorySize, SMT);

    cvt_x_kernel<<<20000, 256>>>(x);
    cvt_w_kernel<<<48, 256>>>(kvw, pw);

    conv_hmma_kernel<<<dim3(313, 2, 4), 256, SMT>>>();
    attn_kernel<<<dim3(625, 2), 256>>>(q, /*head=*/0, /*dil=*/1, /*stage=*/0);
    attn_kernel<<<dim3(625, 2), 256>>>(q, /*head=*/1, /*dil=*/2, /*stage=*/1);
    proj_hmma_kernel<<<625, 256, SMT>>>(pb, out);
}